// round 7
// baseline (speedup 1.0000x reference)
#include <cuda_runtime.h>
#include <math.h>

// Problem constants
#define BN   4096
#define TN   512
#define ZD   64
#define OU   128
#define BERT 768
#define TOUT 513   // T+1 trajectory points
#define GRID 148
#define MAXROWS 28

// Scratch (device globals: no allocation allowed)
__device__ float gZaug[BN * ZD];
__device__ float gPartial[BN];

// tanh(x) = 1 - 2/(exp2(2x*log2e)+1). ex2 + fast divide — EXACT form validated
// on HW in R3 (rel_err 5.93e-7, unchanged vs tanhf).
__device__ __forceinline__ float fast_tanh(float x) {
    float e;
    asm("ex2.approx.f32 %0, %1;" : "=f"(e) : "f"(x * 2.8853900817779268f));
    return 1.0f - __fdividef(2.0f, e + 1.0f);
}

// ---------------------------------------------------------------------------
// Phase A: warp-per-row. h = bert@projW + b -> LN -> +sigma*eps -> denoiser
// -> z_aug (scratch), diff partials, and t=0 outputs.  (validated: ~110us)
// ---------------------------------------------------------------------------
__global__ __launch_bounds__(256) void phaseA_kernel(
    const float* __restrict__ bert, const float* __restrict__ eps,
    const float* __restrict__ projW, const float* __restrict__ projB,
    const float* __restrict__ lnG, const float* __restrict__ lnB,
    const float* __restrict__ lns,
    const float* __restrict__ dW1, const float* __restrict__ db1,
    const float* __restrict__ dW2, const float* __restrict__ db2,
    const float* __restrict__ decW, const float* __restrict__ decB,
    float* __restrict__ outPd, float* __restrict__ outSl)
{
    const unsigned FULL = 0xffffffffu;
    int warp = (blockIdx.x * blockDim.x + threadIdx.x) >> 5;
    int l = threadIdx.x & 31;
    if (warp >= BN) return;
    const int r = warp;
    const int c = 2 * l;

    const float* brow = bert + (size_t)r * BERT;
    float hx = 0.f, hy = 0.f;
    #pragma unroll 4
    for (int k = 0; k < BERT; k++) {
        float bv = __ldg(brow + k);
        float2 wv = *(const float2*)(projW + k * ZD + c);
        hx = fmaf(bv, wv.x, hx);
        hy = fmaf(bv, wv.y, hy);
    }
    hx += projB[c]; hy += projB[c + 1];

    float s = hx + hy;
    #pragma unroll
    for (int o = 16; o; o >>= 1) s += __shfl_xor_sync(FULL, s, o);
    float mu = s * (1.0f / 64.0f);
    float d0 = hx - mu, d1 = hy - mu;
    float ss = d0 * d0 + d1 * d1;
    #pragma unroll
    for (int o = 16; o; o >>= 1) ss += __shfl_xor_sync(FULL, ss, o);
    float var = ss * (1.0f / 64.0f);
    float rs = rsqrtf(var + 1e-5f);
    float zc0 = d0 * rs * lnG[c]     + lnB[c];
    float zc1 = d1 * rs * lnG[c + 1] + lnB[c + 1];

    float sigma = log1pf(expf(lns[0]));
    float zn0 = zc0 + sigma * eps[(size_t)r * ZD + c];
    float zn1 = zc1 + sigma * eps[(size_t)r * ZD + c + 1];

    int j0 = 4 * l;
    float4 a = *(const float4*)(db1 + j0);
    #pragma unroll 4
    for (int k2 = 0; k2 < 32; k2++) {
        float zva = __shfl_sync(FULL, zn0, k2);
        float zvb = __shfl_sync(FULL, zn1, k2);
        int k = 2 * k2;
        float4 w = *(const float4*)(dW1 + k * OU + j0);
        a.x = fmaf(zva, w.x, a.x); a.y = fmaf(zva, w.y, a.y);
        a.z = fmaf(zva, w.z, a.z); a.w = fmaf(zva, w.w, a.w);
        w = *(const float4*)(dW1 + (k + 1) * OU + j0);
        a.x = fmaf(zvb, w.x, a.x); a.y = fmaf(zvb, w.y, a.y);
        a.z = fmaf(zvb, w.z, a.z); a.w = fmaf(zvb, w.w, a.w);
    }
    a.x = a.x / (1.f + expf(-a.x));
    a.y = a.y / (1.f + expf(-a.y));
    a.z = a.z / (1.f + expf(-a.z));
    a.w = a.w / (1.f + expf(-a.w));

    float za0 = db2[c], za1 = db2[c + 1];
    float a1v[4] = {a.x, a.y, a.z, a.w};
    #pragma unroll 2
    for (int k4 = 0; k4 < 32; k4++) {
        #pragma unroll
        for (int j = 0; j < 4; j++) {
            float hv = __shfl_sync(FULL, a1v[j], k4);
            int k = 4 * k4 + j;
            float2 w = *(const float2*)(dW2 + k * ZD + c);
            za0 = fmaf(hv, w.x, za0);
            za1 = fmaf(hv, w.y, za1);
        }
    }

    float dd = (za0 - zc0) * (za0 - zc0) + (za1 - zc1) * (za1 - zc1);
    #pragma unroll
    for (int o = 16; o; o >>= 1) dd += __shfl_xor_sync(FULL, dd, o);
    if (l == 0) gPartial[r] = dd;

    *(float2*)(gZaug + (size_t)r * ZD + c) = make_float2(za0, za1);

    float pd = za0 * decW[c * 2 + 0] + za1 * decW[(c + 1) * 2 + 0];
    float sl = za0 * decW[c * 2 + 1] + za1 * decW[(c + 1) * 2 + 1];
    #pragma unroll
    for (int o = 16; o; o >>= 1) {
        pd += __shfl_xor_sync(FULL, pd, o);
        sl += __shfl_xor_sync(FULL, sl, o);
    }
    if (l == 0) {
        outPd[(size_t)r * TOUT] = pd + decB[0];
        outSl[(size_t)r * TOUT] = sl + decB[1];
    }
}

// ---------------------------------------------------------------------------
// diff_loss final reduction (deterministic, single CTA)
// ---------------------------------------------------------------------------
__global__ void reduceDiff_kernel(float* __restrict__ outDiff)
{
    __shared__ float sh[256];
    float s = 0.f;
    for (int i = threadIdx.x; i < BN; i += 256) s += gPartial[i];
    sh[threadIdx.x] = s;
    __syncthreads();
    for (int step = 128; step; step >>= 1) {
        if (threadIdx.x < step) sh[threadIdx.x] += sh[threadIdx.x + step];
        __syncthreads();
    }
    if (threadIdx.x == 0) outDiff[0] = sh[0] * (1.0f / ((float)BN * (float)ZD));
}

// ---------------------------------------------------------------------------
// Phase B: ODE scan, 148 CTAs (chip-filling). CTA 0..99: 28 rows; 100..147: 27.
// Warps own R in {3,4} rows, balanced so each SMSP (warps w,w+4) carries <=7
// rows. Warp-independent: no __syncthreads in the 512-step loop.
// ---------------------------------------------------------------------------
template<int R>
__device__ __forceinline__ void ode_loop(
    const float* __restrict__ sW1, const float* __restrict__ sW2,
    const float* __restrict__ sW3, const float* __restrict__ sB1,
    const float* __restrict__ sB2, const float* __restrict__ sB3,
    float* __restrict__ sZ, float* __restrict__ sH1, float* __restrict__ sH2,
    int row0, int l, size_t gRow0,
    float2 dv0, float2 dv1, float db0, float db1v,
    float* __restrict__ outPd, float* __restrict__ outSl)
{
    const int c4 = l * 4;
    const int c2 = l * 2;
    const float dt = 1.0f / (float)TN;
    const unsigned FULL = 0xffffffffu;

    for (int t = 0; t < TN; t++) {
        // ===== GEMM1: h1 = tanh(z @ W1 + b1), K=64 -> 128 cols =====
        {
            float4 acc[R];
            float4 bb = *(const float4*)(sB1 + c4);
            #pragma unroll
            for (int rr = 0; rr < R; rr++) acc[rr] = bb;
            #pragma unroll 2
            for (int k = 0; k < ZD; k += 4) {
                float4 zr[R];
                #pragma unroll
                for (int rr = 0; rr < R; rr++)
                    zr[rr] = *(const float4*)(sZ + (row0 + rr) * ZD + k);
                #pragma unroll
                for (int kk = 0; kk < 4; kk++) {
                    float4 wv = *(const float4*)(sW1 + (k + kk) * OU + c4);
                    #pragma unroll
                    for (int rr = 0; rr < R; rr++) {
                        float zv = (kk == 0) ? zr[rr].x : (kk == 1) ? zr[rr].y
                                 : (kk == 2) ? zr[rr].z : zr[rr].w;
                        acc[rr].x = fmaf(zv, wv.x, acc[rr].x);
                        acc[rr].y = fmaf(zv, wv.y, acc[rr].y);
                        acc[rr].z = fmaf(zv, wv.z, acc[rr].z);
                        acc[rr].w = fmaf(zv, wv.w, acc[rr].w);
                    }
                }
            }
            #pragma unroll
            for (int rr = 0; rr < R; rr++) {
                float4 v = acc[rr];
                v.x = fast_tanh(v.x); v.y = fast_tanh(v.y);
                v.z = fast_tanh(v.z); v.w = fast_tanh(v.w);
                *(float4*)(sH1 + (row0 + rr) * OU + c4) = v;
            }
            __syncwarp();
        }

        // ===== GEMM2: h2 = tanh(h1 @ W2 + b2), K=128 -> 128 cols =====
        {
            float4 acc[R];
            float4 bb = *(const float4*)(sB2 + c4);
            #pragma unroll
            for (int rr = 0; rr < R; rr++) acc[rr] = bb;
            #pragma unroll 2
            for (int k = 0; k < OU; k += 4) {
                float4 hr[R];
                #pragma unroll
                for (int rr = 0; rr < R; rr++)
                    hr[rr] = *(const float4*)(sH1 + (row0 + rr) * OU + k);
                #pragma unroll
                for (int kk = 0; kk < 4; kk++) {
                    float4 wv = *(const float4*)(sW2 + (k + kk) * OU + c4);
                    #pragma unroll
                    for (int rr = 0; rr < R; rr++) {
                        float hv = (kk == 0) ? hr[rr].x : (kk == 1) ? hr[rr].y
                                 : (kk == 2) ? hr[rr].z : hr[rr].w;
                        acc[rr].x = fmaf(hv, wv.x, acc[rr].x);
                        acc[rr].y = fmaf(hv, wv.y, acc[rr].y);
                        acc[rr].z = fmaf(hv, wv.z, acc[rr].z);
                        acc[rr].w = fmaf(hv, wv.w, acc[rr].w);
                    }
                }
            }
            #pragma unroll
            for (int rr = 0; rr < R; rr++) {
                float4 v = acc[rr];
                v.x = fast_tanh(v.x); v.y = fast_tanh(v.y);
                v.z = fast_tanh(v.z); v.w = fast_tanh(v.w);
                *(float4*)(sH2 + (row0 + rr) * OU + c4) = v;
            }
            __syncwarp();
        }

        // ===== GEMM3: f = h2 @ W3 + b3 (64 cols), z update, decode =====
        {
            float2 f[R];
            float2 b3v = *(const float2*)(sB3 + c2);
            #pragma unroll
            for (int rr = 0; rr < R; rr++) f[rr] = b3v;
            #pragma unroll 2
            for (int k = 0; k < OU; k += 4) {
                float4 hr[R];
                #pragma unroll
                for (int rr = 0; rr < R; rr++)
                    hr[rr] = *(const float4*)(sH2 + (row0 + rr) * OU + k);
                #pragma unroll
                for (int kk = 0; kk < 4; kk++) {
                    float2 wv = *(const float2*)(sW3 + (k + kk) * ZD + c2);
                    #pragma unroll
                    for (int rr = 0; rr < R; rr++) {
                        float hv = (kk == 0) ? hr[rr].x : (kk == 1) ? hr[rr].y
                                 : (kk == 2) ? hr[rr].z : hr[rr].w;
                        f[rr].x = fmaf(hv, wv.x, f[rr].x);
                        f[rr].y = fmaf(hv, wv.y, f[rr].y);
                    }
                }
            }
            float pd[R], sl[R];
            #pragma unroll
            for (int rr = 0; rr < R; rr++) {
                float2 zo = *(const float2*)(sZ + (row0 + rr) * ZD + c2);
                zo.x = fmaf(dt, f[rr].x, zo.x);
                zo.y = fmaf(dt, f[rr].y, zo.y);
                *(float2*)(sZ + (row0 + rr) * ZD + c2) = zo;
                pd[rr] = zo.x * dv0.x + zo.y * dv0.y;
                sl[rr] = zo.x * dv1.x + zo.y * dv1.y;
            }
            __syncwarp();
            #pragma unroll
            for (int rr = 0; rr < R; rr++) {
                float p = pd[rr], q = sl[rr];
                #pragma unroll
                for (int o = 16; o; o >>= 1) {
                    p += __shfl_xor_sync(FULL, p, o);
                    q += __shfl_xor_sync(FULL, q, o);
                }
                if (l == 0) {
                    size_t row = gRow0 + rr;
                    outPd[row * TOUT + (t + 1)] = p + db0;
                    outSl[row * TOUT + (t + 1)] = q + db1v;
                }
            }
        }
    }
}

// rows per warp: balanced so SMSP pairs (w, w+4) total <= 7 rows.
// cnt=28: {4,4,3,3,3,3,4,4}; cnt=27: {4,4,3,3,3,3,3,4}
__device__ __forceinline__ int rows_of(int w, int cnt) {
    if (cnt == 28) return (w <= 1 || w >= 6) ? 4 : 3;
    return (w <= 1 || w == 7) ? 4 : 3;
}

__global__ __launch_bounds__(256, 1) void ode_kernel(
    const float* __restrict__ oW1, const float* __restrict__ ob1,
    const float* __restrict__ oW2, const float* __restrict__ ob2,
    const float* __restrict__ oW3, const float* __restrict__ ob3,
    const float* __restrict__ decW, const float* __restrict__ decB,
    float* __restrict__ outPd, float* __restrict__ outSl)
{
    extern __shared__ float sm[];
    float* sW1 = sm;                       // 64*128
    float* sW2 = sW1 + ZD * OU;            // 128*128
    float* sW3 = sW2 + OU * OU;            // 128*64
    float* sB1 = sW3 + OU * ZD;            // 128
    float* sB2 = sB1 + OU;                 // 128
    float* sB3 = sB2 + OU;                 // 64
    float* sD0 = sB3 + ZD;                 // 64
    float* sD1 = sD0 + ZD;                 // 64
    float* sZ  = sD1 + ZD;                 // 28*64
    float* sH1 = sZ + MAXROWS * ZD;        // 28*128
    float* sH2 = sH1 + MAXROWS * OU;       // 28*128

    const int tid = threadIdx.x;
    const int cta = blockIdx.x;
    const int cnt     = (cta < 100) ? 28 : 27;
    const int rowBase = (cta < 100) ? 28 * cta : 2800 + 27 * (cta - 100);

    // cooperative weight/state loads (float4)
    for (int i = tid; i < (ZD * OU) / 4; i += 256) ((float4*)sW1)[i] = ((const float4*)oW1)[i];
    for (int i = tid; i < (OU * OU) / 4; i += 256) ((float4*)sW2)[i] = ((const float4*)oW2)[i];
    for (int i = tid; i < (OU * ZD) / 4; i += 256) ((float4*)sW3)[i] = ((const float4*)oW3)[i];
    if (tid < OU) { sB1[tid] = ob1[tid]; sB2[tid] = ob2[tid]; }
    if (tid < ZD) { sB3[tid] = ob3[tid]; sD0[tid] = decW[2 * tid]; sD1[tid] = decW[2 * tid + 1]; }
    for (int i = tid; i < cnt * (ZD / 4); i += 256)
        ((float4*)sZ)[i] = ((const float4*)(gZaug + (size_t)rowBase * ZD))[i];
    __syncthreads();

    const int w = tid >> 5;
    const int l = tid & 31;
    int row0 = 0;
    for (int j = 0; j < 8; j++) if (j < w) row0 += rows_of(j, cnt);
    const int R = rows_of(w, cnt);

    const int c2 = l * 2;
    const float2 dv0 = make_float2(sD0[c2], sD0[c2 + 1]);
    const float2 dv1 = make_float2(sD1[c2], sD1[c2 + 1]);
    const float db0 = decB[0], db1v = decB[1];
    const size_t gRow0 = (size_t)(rowBase + row0);

    if (R == 4)
        ode_loop<4>(sW1, sW2, sW3, sB1, sB2, sB3, sZ, sH1, sH2,
                    row0, l, gRow0, dv0, dv1, db0, db1v, outPd, outSl);
    else
        ode_loop<3>(sW1, sW2, sW3, sB1, sB2, sB3, sZ, sH1, sH2,
                    row0, l, gRow0, dv0, dv1, db0, db1v, outPd, outSl);
}

// ---------------------------------------------------------------------------
// Launch
// ---------------------------------------------------------------------------
extern "C" void kernel_launch(void* const* d_in, const int* in_sizes, int n_in,
                              void* d_out, int out_size)
{
    const float* bert  = (const float*)d_in[0];
    const float* eps   = (const float*)d_in[3];
    const float* projW = (const float*)d_in[4];
    const float* projB = (const float*)d_in[5];
    const float* lnG   = (const float*)d_in[6];
    const float* lnB   = (const float*)d_in[7];
    const float* lns   = (const float*)d_in[8];
    const float* dW1   = (const float*)d_in[9];
    const float* db1   = (const float*)d_in[10];
    const float* dW2   = (const float*)d_in[11];
    const float* db2   = (const float*)d_in[12];
    const float* oW1   = (const float*)d_in[13];
    const float* ob1   = (const float*)d_in[14];
    const float* oW2   = (const float*)d_in[15];
    const float* ob2   = (const float*)d_in[16];
    const float* oW3   = (const float*)d_in[17];
    const float* ob3   = (const float*)d_in[18];
    const float* decW  = (const float*)d_in[19];
    const float* decB  = (const float*)d_in[20];

    float* out    = (float*)d_out;
    float* outPd  = out;
    float* outSl  = out + (size_t)BN * TOUT;
    float* outDif = out + 2 * (size_t)BN * TOUT;

    phaseA_kernel<<<512, 256>>>(bert, eps, projW, projB, lnG, lnB, lns,
                                dW1, db1, dW2, db2, decW, decB, outPd, outSl);
    reduceDiff_kernel<<<1, 256>>>(outDif);

    size_t smemFloats = (size_t)(ZD * OU + OU * OU + OU * ZD        // weights
                                 + OU + OU + ZD + ZD + ZD           // biases + dec
                                 + MAXROWS * ZD + MAXROWS * OU + MAXROWS * OU);
    size_t smemBytes = smemFloats * sizeof(float);
    cudaFuncSetAttribute(ode_kernel, cudaFuncAttributeMaxDynamicSharedMemorySize,
                         (int)smemBytes);
    ode_kernel<<<GRID, 256, smemBytes>>>(oW1, ob1, oW2, ob2, oW3, ob3,
                                         decW, decB, outPd, outSl);
}

// round 9
// speedup vs baseline: 1.1457x; 1.1457x over previous
#include <cuda_runtime.h>
#include <math.h>
#include <stdint.h>

// Problem constants
#define BN   4096
#define TN   512
#define ZD   64
#define OU   128
#define BERT 768
#define TOUT 513

// Scratch (device globals: no allocation allowed)
__device__ float gZaug[BN * ZD];
__device__ float gPartial[BN];

// tanh(x) = 1 - 2/(exp2(2x*log2e)+1). HW-validated (R3/R6).
__device__ __forceinline__ float fast_tanh(float x) {
    float e;
    asm("ex2.approx.f32 %0, %1;" : "=f"(e) : "f"(x * 2.8853900817779268f));
    return 1.0f - __fdividef(2.0f, e + 1.0f);
}

__device__ __forceinline__ uint32_t smem_u32(const void* p) {
    uint32_t a;
    asm("{ .reg .u64 t; cvta.to.shared.u64 t, %1; cvt.u32.u64 %0, t; }"
        : "=r"(a) : "l"(p));
    return a;
}

// ldmatrix x4: 4 8x8 b16 tiles; lanes 0-7 address m0 rows, 8-15 m1, ...
__device__ __forceinline__ void ldsm4(uint32_t& r0, uint32_t& r1,
                                      uint32_t& r2, uint32_t& r3, uint32_t addr) {
    asm volatile("ldmatrix.sync.aligned.m8n8.x4.shared.b16 {%0,%1,%2,%3}, [%4];"
                 : "=r"(r0), "=r"(r1), "=r"(r2), "=r"(r3) : "r"(addr));
}

// bf16 mma with fp32 accumulate (compute_80+, valid on plain sm_103)
__device__ __forceinline__ void mma_bf16(float c[4], uint32_t a0, uint32_t a1,
                                         uint32_t a2, uint32_t a3,
                                         uint32_t b0, uint32_t b1) {
    asm volatile("mma.sync.aligned.m16n8k16.row.col.f32.bf16.bf16.f32 "
                 "{%0,%1,%2,%3}, {%4,%5,%6,%7}, {%8,%9}, {%0,%1,%2,%3};"
                 : "+f"(c[0]), "+f"(c[1]), "+f"(c[2]), "+f"(c[3])
                 : "r"(a0), "r"(a1), "r"(a2), "r"(a3), "r"(b0), "r"(b1));
}

// fp32 pair -> bf16x2 hi (truncation) + bf16x2 lo (exact residual, truncated)
__device__ __forceinline__ void pack2(float v0, float v1, uint32_t& h, uint32_t& l) {
    uint32_t u0 = __float_as_uint(v0), u1 = __float_as_uint(v1);
    h = __byte_perm(u0, u1, 0x7632);
    float l0 = v0 - __uint_as_float(u0 & 0xFFFF0000u);
    float l1 = v1 - __uint_as_float(u1 & 0xFFFF0000u);
    l = __byte_perm(__float_as_uint(l0), __float_as_uint(l1), 0x7632);
}

// ---------------------------------------------------------------------------
// Phase A: warp-per-row (unchanged, validated ~110us)
// ---------------------------------------------------------------------------
__global__ __launch_bounds__(256) void phaseA_kernel(
    const float* __restrict__ bert, const float* __restrict__ eps,
    const float* __restrict__ projW, const float* __restrict__ projB,
    const float* __restrict__ lnG, const float* __restrict__ lnB,
    const float* __restrict__ lns,
    const float* __restrict__ dW1, const float* __restrict__ db1,
    const float* __restrict__ dW2, const float* __restrict__ db2,
    const float* __restrict__ decW, const float* __restrict__ decB,
    float* __restrict__ outPd, float* __restrict__ outSl)
{
    const unsigned FULL = 0xffffffffu;
    int warp = (blockIdx.x * blockDim.x + threadIdx.x) >> 5;
    int l = threadIdx.x & 31;
    if (warp >= BN) return;
    const int r = warp;
    const int c = 2 * l;

    const float* brow = bert + (size_t)r * BERT;
    float hx = 0.f, hy = 0.f;
    #pragma unroll 4
    for (int k = 0; k < BERT; k++) {
        float bv = __ldg(brow + k);
        float2 wv = *(const float2*)(projW + k * ZD + c);
        hx = fmaf(bv, wv.x, hx);
        hy = fmaf(bv, wv.y, hy);
    }
    hx += projB[c]; hy += projB[c + 1];

    float s = hx + hy;
    #pragma unroll
    for (int o = 16; o; o >>= 1) s += __shfl_xor_sync(FULL, s, o);
    float mu = s * (1.0f / 64.0f);
    float d0 = hx - mu, d1 = hy - mu;
    float ss = d0 * d0 + d1 * d1;
    #pragma unroll
    for (int o = 16; o; o >>= 1) ss += __shfl_xor_sync(FULL, ss, o);
    float var = ss * (1.0f / 64.0f);
    float rs = rsqrtf(var + 1e-5f);
    float zc0 = d0 * rs * lnG[c]     + lnB[c];
    float zc1 = d1 * rs * lnG[c + 1] + lnB[c + 1];

    float sigma = log1pf(expf(lns[0]));
    float zn0 = zc0 + sigma * eps[(size_t)r * ZD + c];
    float zn1 = zc1 + sigma * eps[(size_t)r * ZD + c + 1];

    int j0 = 4 * l;
    float4 a = *(const float4*)(db1 + j0);
    #pragma unroll 4
    for (int k2 = 0; k2 < 32; k2++) {
        float zva = __shfl_sync(FULL, zn0, k2);
        float zvb = __shfl_sync(FULL, zn1, k2);
        int k = 2 * k2;
        float4 w = *(const float4*)(dW1 + k * OU + j0);
        a.x = fmaf(zva, w.x, a.x); a.y = fmaf(zva, w.y, a.y);
        a.z = fmaf(zva, w.z, a.z); a.w = fmaf(zva, w.w, a.w);
        w = *(const float4*)(dW1 + (k + 1) * OU + j0);
        a.x = fmaf(zvb, w.x, a.x); a.y = fmaf(zvb, w.y, a.y);
        a.z = fmaf(zvb, w.z, a.z); a.w = fmaf(zvb, w.w, a.w);
    }
    a.x = a.x / (1.f + expf(-a.x));
    a.y = a.y / (1.f + expf(-a.y));
    a.z = a.z / (1.f + expf(-a.z));
    a.w = a.w / (1.f + expf(-a.w));

    float za0 = db2[c], za1 = db2[c + 1];
    float a1v[4] = {a.x, a.y, a.z, a.w};
    #pragma unroll 2
    for (int k4 = 0; k4 < 32; k4++) {
        #pragma unroll
        for (int j = 0; j < 4; j++) {
            float hv = __shfl_sync(FULL, a1v[j], k4);
            int k = 4 * k4 + j;
            float2 w = *(const float2*)(dW2 + k * ZD + c);
            za0 = fmaf(hv, w.x, za0);
            za1 = fmaf(hv, w.y, za1);
        }
    }

    float dd = (za0 - zc0) * (za0 - zc0) + (za1 - zc1) * (za1 - zc1);
    #pragma unroll
    for (int o = 16; o; o >>= 1) dd += __shfl_xor_sync(FULL, dd, o);
    if (l == 0) gPartial[r] = dd;

    *(float2*)(gZaug + (size_t)r * ZD + c) = make_float2(za0, za1);

    float pd = za0 * decW[c * 2 + 0] + za1 * decW[(c + 1) * 2 + 0];
    float sl = za0 * decW[c * 2 + 1] + za1 * decW[(c + 1) * 2 + 1];
    #pragma unroll
    for (int o = 16; o; o >>= 1) {
        pd += __shfl_xor_sync(FULL, pd, o);
        sl += __shfl_xor_sync(FULL, sl, o);
    }
    if (l == 0) {
        outPd[(size_t)r * TOUT] = pd + decB[0];
        outSl[(size_t)r * TOUT] = sl + decB[1];
    }
}

__global__ void reduceDiff_kernel(float* __restrict__ outDiff)
{
    __shared__ float sh[256];
    float s = 0.f;
    for (int i = threadIdx.x; i < BN; i += 256) s += gPartial[i];
    sh[threadIdx.x] = s;
    __syncthreads();
    for (int step = 128; step; step >>= 1) {
        if (threadIdx.x < step) sh[threadIdx.x] += sh[threadIdx.x + step];
        __syncthreads();
    }
    if (threadIdx.x == 0) outDiff[0] = sh[0] * (1.0f / ((float)BN * (float)ZD));
}

// ---------------------------------------------------------------------------
// SMEM layout (byte offsets from 1024-aligned base). Weights stored
// TRANSPOSED, n-major: row n holds K bf16, row stride padded +16B so LDSM
// rows land on distinct banks (stride mod 128 == 16).
// ---------------------------------------------------------------------------
#define S_W1 144   // W1: 128 n-rows x 64k*2B + 16 pad
#define S_W2 272   // W2: 128 n-rows x 128k*2B + 16
#define S_W3 272   // W3: 64 n-rows
#define OFF_W1H 0
#define OFF_W1L (OFF_W1H + 128 * S_W1)          // 18432
#define OFF_W2H (OFF_W1L + 128 * S_W1)          // 36864
#define OFF_W2L (OFF_W2H + 128 * S_W2)          // 71680
#define OFF_W3H (OFF_W2L + 128 * S_W2)          // 106496
#define OFF_W3L (OFF_W3H + 64 * S_W3)           // 123904
#define OFF_B1  (OFF_W3L + 64 * S_W3)           // 141312
#define OFF_B2  (OFF_B1 + 512)
#define OFF_B3  (OFF_B2 + 512)
#define OFF_D0  (OFF_B3 + 256)
#define OFF_D1  (OFF_D0 + 256)
#define SMEM_USED (OFF_D1 + 256)                // 143104

// One weight pass: for each k-chunk kc and n-tile pair (j,j+1), ldsm x4 and
// accumulate. a[] layout: a[4*kc + {0..3}] = A-frags for that k-chunk.
template<int NKC, int NJ, int STRIDE>
__device__ __forceinline__ void gemm_pass(float D[][4], const uint32_t* a,
                                          uint32_t base) {
    #pragma unroll
    for (int kc = 0; kc < NKC; kc++) {
        #pragma unroll
        for (int j = 0; j < NJ; j += 2) {
            uint32_t b0, b1, b2, b3;
            ldsm4(b0, b1, b2, b3, base + j * 8 * STRIDE + kc * 32);
            mma_bf16(D[j],     a[4*kc+0], a[4*kc+1], a[4*kc+2], a[4*kc+3], b0, b1);
            mma_bf16(D[j + 1], a[4*kc+0], a[4*kc+1], a[4*kc+2], a[4*kc+3], b2, b3);
        }
    }
}

template<int NJ>
__device__ __forceinline__ void init_bias(float D[][4], const char* sB, int tq) {
    #pragma unroll
    for (int j = 0; j < NJ; j++) {
        float2 b = *(const float2*)(sB + (8 * j + 2 * tq) * 4);
        D[j][0] = b.x; D[j][1] = b.y; D[j][2] = b.x; D[j][3] = b.y;
    }
}

template<int NJ>
__device__ __forceinline__ void epi_tanh(float D[][4], uint32_t* hh, uint32_t* hl) {
    #pragma unroll
    for (int j = 0; j < NJ; j++) {
        float v0 = fast_tanh(D[j][0]);
        float v1 = fast_tanh(D[j][1]);
        float v2 = fast_tanh(D[j][2]);
        float v3 = fast_tanh(D[j][3]);
        pack2(v0, v1, hh[2*j],     hl[2*j]);
        pack2(v2, v3, hh[2*j + 1], hl[2*j + 1]);
    }
}

// ---------------------------------------------------------------------------
// Phase B: mma.sync ODE scan. 128 CTAs x 64 threads; each warp owns 16 rows
// and ALL output columns -> activations chain GEMM->GEMM in registers
// (D-frag layout == A-frag layout). No barriers in the 512-step loop.
// ---------------------------------------------------------------------------
__global__ __launch_bounds__(64, 1) void ode_mma_kernel(
    const float* __restrict__ oW1, const float* __restrict__ ob1,
    const float* __restrict__ oW2, const float* __restrict__ ob2,
    const float* __restrict__ oW3, const float* __restrict__ ob3,
    const float* __restrict__ decW, const float* __restrict__ decB,
    float* __restrict__ outPd, float* __restrict__ outSl)
{
    extern __shared__ char smraw[];
    uint32_t sb0 = smem_u32(smraw);
    uint32_t sbase = (sb0 + 1023) & ~1023u;
    char* sm = smraw + (sbase - sb0);
    const int tid = threadIdx.x;

    // ---- Fill transposed hi/lo weight tiles (one-time) ----
    for (int idx = tid; idx < ZD * OU; idx += 64) {           // W1 [64k][128n]
        int k = idx >> 7, n = idx & 127;
        float v = oW1[idx];
        uint32_t u = __float_as_uint(v);
        float lo = v - __uint_as_float(u & 0xFFFF0000u);
        *(uint16_t*)(sm + OFF_W1H + n * S_W1 + k * 2) = (uint16_t)(u >> 16);
        *(uint16_t*)(sm + OFF_W1L + n * S_W1 + k * 2) = (uint16_t)(__float_as_uint(lo) >> 16);
    }
    for (int idx = tid; idx < OU * OU; idx += 64) {           // W2 [128][128]
        int k = idx >> 7, n = idx & 127;
        float v = oW2[idx];
        uint32_t u = __float_as_uint(v);
        float lo = v - __uint_as_float(u & 0xFFFF0000u);
        *(uint16_t*)(sm + OFF_W2H + n * S_W2 + k * 2) = (uint16_t)(u >> 16);
        *(uint16_t*)(sm + OFF_W2L + n * S_W2 + k * 2) = (uint16_t)(__float_as_uint(lo) >> 16);
    }
    for (int idx = tid; idx < OU * ZD; idx += 64) {           // W3 [128k][64n]
        int k = idx >> 6, n = idx & 63;
        float v = oW3[idx];
        uint32_t u = __float_as_uint(v);
        float lo = v - __uint_as_float(u & 0xFFFF0000u);
        *(uint16_t*)(sm + OFF_W3H + n * S_W3 + k * 2) = (uint16_t)(u >> 16);
        *(uint16_t*)(sm + OFF_W3L + n * S_W3 + k * 2) = (uint16_t)(__float_as_uint(lo) >> 16);
    }
    for (int i = tid; i < OU; i += 64) {
        ((float*)(sm + OFF_B1))[i] = ob1[i];
        ((float*)(sm + OFF_B2))[i] = ob2[i];
    }
    if (tid < ZD) {
        ((float*)(sm + OFF_B3))[tid] = ob3[tid];
        ((float*)(sm + OFF_D0))[tid] = decW[2 * tid];
        ((float*)(sm + OFF_D1))[tid] = decW[2 * tid + 1];
    }
    __syncthreads();

    const int wi = tid >> 5, l = tid & 31;
    const int g = l >> 2, tq = l & 3;
    const int base = blockIdx.x * 32 + wi * 16;

    // LDSM per-lane offset: matrices (j,h0),(j,h1),(j+1,h0),(j+1,h1)
    const int laneRow = l & 7, mi = l >> 3;
    const int jo = mi >> 1, hf = mi & 1;
    const uint32_t off1 = (uint32_t)((jo * 8 + laneRow) * S_W1 + hf * 16);
    const uint32_t off2 = (uint32_t)((jo * 8 + laneRow) * S_W2 + hf * 16);
    const uint32_t aW1H = sbase + OFF_W1H + off1, aW1L = sbase + OFF_W1L + off1;
    const uint32_t aW2H = sbase + OFF_W2H + off2, aW2L = sbase + OFF_W2L + off2;
    const uint32_t aW3H = sbase + OFF_W3H + off2, aW3L = sbase + OFF_W3L + off2;

    // fp32 z state in D-fragment layout: 8 tiles x {c0..c3}
    float z[8][4];
    #pragma unroll
    for (int j = 0; j < 8; j++) {
        float2 p = *(const float2*)(gZaug + (size_t)(base + g) * ZD + 8 * j + 2 * tq);
        float2 q = *(const float2*)(gZaug + (size_t)(base + g + 8) * ZD + 8 * j + 2 * tq);
        z[j][0] = p.x; z[j][1] = p.y; z[j][2] = q.x; z[j][3] = q.y;
    }

    const float dt = 1.0f / (float)TN;
    const float db0 = decB[0], db1v = decB[1];
    const unsigned FULL = 0xffffffffu;

    for (int t = 0; t < TN; t++) {
        // ===== GEMM1: D = z @ W1 + b1 (K=64 -> N=128) =====
        float D[16][4];
        init_bias<16>(D, sm + OFF_B1, tq);
        uint32_t ah[16], al[16];
        #pragma unroll
        for (int kc = 0; kc < 4; kc++) {
            pack2(z[2*kc][0],   z[2*kc][1],   ah[4*kc+0], al[4*kc+0]);
            pack2(z[2*kc][2],   z[2*kc][3],   ah[4*kc+1], al[4*kc+1]);
            pack2(z[2*kc+1][0], z[2*kc+1][1], ah[4*kc+2], al[4*kc+2]);
            pack2(z[2*kc+1][2], z[2*kc+1][3], ah[4*kc+3], al[4*kc+3]);
        }
        gemm_pass<4, 16, S_W1>(D, ah, aW1H);
        gemm_pass<4, 16, S_W1>(D, ah, aW1L);
        gemm_pass<4, 16, S_W1>(D, al, aW1H);

        uint32_t h1h[32], h1l[32];
        epi_tanh<16>(D, h1h, h1l);

        // ===== GEMM2: D = h1 @ W2 + b2 (K=128 -> N=128) =====
        init_bias<16>(D, sm + OFF_B2, tq);
        gemm_pass<8, 16, S_W2>(D, h1h, aW2H);
        gemm_pass<8, 16, S_W2>(D, h1h, aW2L);
        gemm_pass<8, 16, S_W2>(D, h1l, aW2H);

        uint32_t h2h[32], h2l[32];
        epi_tanh<16>(D, h2h, h2l);

        // ===== GEMM3: D3 = h2 @ W3 + b3 (K=128 -> N=64) =====
        float D3[8][4];
        init_bias<8>(D3, sm + OFF_B3, tq);
        gemm_pass<8, 8, S_W3>(D3, h2h, aW3H);
        gemm_pass<8, 8, S_W3>(D3, h2h, aW3L);
        gemm_pass<8, 8, S_W3>(D3, h2l, aW3H);

        // ===== epi3: z += dt*f; decode; store =====
        float pdA = 0.f, pdB = 0.f, slA = 0.f, slB = 0.f;
        #pragma unroll
        for (int j = 0; j < 8; j++) {
            z[j][0] = fmaf(dt, D3[j][0], z[j][0]);
            z[j][1] = fmaf(dt, D3[j][1], z[j][1]);
            z[j][2] = fmaf(dt, D3[j][2], z[j][2]);
            z[j][3] = fmaf(dt, D3[j][3], z[j][3]);
            float2 d0 = *(const float2*)(sm + OFF_D0 + (8 * j + 2 * tq) * 4);
            float2 d1 = *(const float2*)(sm + OFF_D1 + (8 * j + 2 * tq) * 4);
            pdA += z[j][0] * d0.x + z[j][1] * d0.y;
            pdB += z[j][2] * d0.x + z[j][3] * d0.y;
            slA += z[j][0] * d1.x + z[j][1] * d1.y;
            slB += z[j][2] * d1.x + z[j][3] * d1.y;
        }
        pdA += __shfl_xor_sync(FULL, pdA, 1); pdA += __shfl_xor_sync(FULL, pdA, 2);
        pdB += __shfl_xor_sync(FULL, pdB, 1); pdB += __shfl_xor_sync(FULL, pdB, 2);
        slA += __shfl_xor_sync(FULL, slA, 1); slA += __shfl_xor_sync(FULL, slA, 2);
        slB += __shfl_xor_sync(FULL, slB, 1); slB += __shfl_xor_sync(FULL, slB, 2);
        if (tq == 0) {
            size_t r0 = (size_t)(base + g), r1 = r0 + 8;
            outPd[r0 * TOUT + t + 1] = pdA + db0;
            outSl[r0 * TOUT + t + 1] = slA + db1v;
            outPd[r1 * TOUT + t + 1] = pdB + db0;
            outSl[r1 * TOUT + t + 1] = slB + db1v;
        }
    }
}

// ---------------------------------------------------------------------------
// Launch
// ---------------------------------------------------------------------------
extern "C" void kernel_launch(void* const* d_in, const int* in_sizes, int n_in,
                              void* d_out, int out_size)
{
    const float* bert  = (const float*)d_in[0];
    const float* eps   = (const float*)d_in[3];
    const float* projW = (const float*)d_in[4];
    const float* projB = (const float*)d_in[5];
    const float* lnG   = (const float*)d_in[6];
    const float* lnB   = (const float*)d_in[7];
    const float* lns   = (const float*)d_in[8];
    const float* dW1   = (const float*)d_in[9];
    const float* db1   = (const float*)d_in[10];
    const float* dW2   = (const float*)d_in[11];
    const float* db2   = (const float*)d_in[12];
    const float* oW1   = (const float*)d_in[13];
    const float* ob1   = (const float*)d_in[14];
    const float* oW2   = (const float*)d_in[15];
    const float* ob2   = (const float*)d_in[16];
    const float* oW3   = (const float*)d_in[17];
    const float* ob3   = (const float*)d_in[18];
    const float* decW  = (const float*)d_in[19];
    const float* decB  = (const float*)d_in[20];

    float* out    = (float*)d_out;
    float* outPd  = out;
    float* outSl  = out + (size_t)BN * TOUT;
    float* outDif = out + 2 * (size_t)BN * TOUT;

    phaseA_kernel<<<512, 256>>>(bert, eps, projW, projB, lnG, lnB, lns,
                                dW1, db1, dW2, db2, decW, decB, outPd, outSl);
    reduceDiff_kernel<<<1, 256>>>(outDif);

    int smemBytes = 1024 + SMEM_USED;
    cudaFuncSetAttribute(ode_mma_kernel, cudaFuncAttributeMaxDynamicSharedMemorySize,
                         smemBytes);
    ode_mma_kernel<<<BN / 32, 64, smemBytes>>>(oW1, ob1, oW2, ob2, oW3, ob3,
                                               decW, decB, outPd, outSl);
}